// round 8
// baseline (speedup 1.0000x reference)
#include <cuda_runtime.h>
#include <math.h>
#include <stdint.h>

#define TT 2048
#define DD 3584
#define NH 28
#define KH 4
#define HD 128
#define GQ 7

// scratch (static __device__ arrays: allocation-free)
__device__ float g_q[(size_t)NH * TT * HD];
__device__ float g_k[(size_t)KH * TT * HD];
__device__ float g_v[(size_t)KH * TT * HD];
__device__ float g_ctx[(size_t)TT * DD];

// ---------------------------------------------------------------------------
// TF32 helpers: error-compensated split (3xTF32)
// hi = round-to-nearest tf32(x); lo = x - hi (exact, Sterbenz). lo is fed raw;
// HW truncation of lo's low bits contributes only ~2^-23 relative error.
// ---------------------------------------------------------------------------
__device__ __forceinline__ void split_tf32(float x, uint32_t& hi, uint32_t& lo) {
    uint32_t h;
    asm("cvt.rna.tf32.f32 %0, %1;" : "=r"(h) : "f"(x));
    hi = h;
    lo = __float_as_uint(x - __uint_as_float(h));
}

__device__ __forceinline__ void mma_tf32(float c[4],
                                         uint32_t a0, uint32_t a1, uint32_t a2, uint32_t a3,
                                         uint32_t b0, uint32_t b1)
{
    asm volatile(
        "mma.sync.aligned.m16n8k8.row.col.f32.tf32.tf32.f32 "
        "{%0,%1,%2,%3},{%4,%5,%6,%7},{%8,%9},{%0,%1,%2,%3};"
        : "+f"(c[0]), "+f"(c[1]), "+f"(c[2]), "+f"(c[3])
        : "r"(a0), "r"(a1), "r"(a2), "r"(a3), "r"(b0), "r"(b1));
}

// 3 MMAs: cross terms first, then main
__device__ __forceinline__ void mma3_tf32(float c[4],
                                          const uint32_t ah[4], const uint32_t al[4],
                                          uint32_t b0h, uint32_t b1h,
                                          uint32_t b0l, uint32_t b1l)
{
    mma_tf32(c, al[0], al[1], al[2], al[3], b0h, b1h);
    mma_tf32(c, ah[0], ah[1], ah[2], ah[3], b0l, b1l);
    mma_tf32(c, ah[0], ah[1], ah[2], ah[3], b0h, b1h);
}

// ---------------------------------------------------------------------------
// 3xTF32 GEMM core: C[128 x 128] = X[128 x DD] * W[DD x 128](slice) (+ bias)
// 256 threads = 8 warps (4m x 2n). Each warp: 32 rows x 64 cols.
// Xs[row][36]: A-frag reads bank-conflict-free ((4r+c)%32).
// Ws[k][136]:  B-frag reads bank-conflict-free ((8k+n)%32).
// ---------------------------------------------------------------------------
#define XS_STRIDE 36
#define WS_STRIDE 136

template<bool HAS_BIAS>
__device__ __forceinline__ void gemm_core_tf32(
    const float* __restrict__ Xbase,
    const float* __restrict__ Wbase, int ldw,
    const float* __restrict__ bias,
    float* __restrict__ Obase, int ldo)
{
    __shared__ float Xs[128 * XS_STRIDE];
    __shared__ float Ws[32 * WS_STRIDE];

    int tid  = threadIdx.x;
    int warp = tid >> 5, lane = tid & 31;
    int wm = warp >> 1;        // 0..3 -> rows wm*32
    int wn = warp & 1;         // 0..1 -> cols wn*64
    int g  = lane >> 2;        // 0..7
    int tg = lane & 3;         // 0..3

    float C[2][8][4];
#pragma unroll
    for (int mt = 0; mt < 2; mt++)
#pragma unroll
        for (int nt = 0; nt < 8; nt++)
#pragma unroll
            for (int r = 0; r < 4; r++) C[mt][nt][r] = 0.f;

    for (int k0 = 0; k0 < DD; k0 += 32) {
        // stage X tile: 128 rows x 32 cols
#pragma unroll
        for (int it = 0; it < 4; it++) {
            int l = tid + it * 256;
            int row = l >> 3, c4 = l & 7;
            float4 v = *(const float4*)(Xbase + (size_t)row * DD + k0 + c4 * 4);
            *(float4*)&Xs[row * XS_STRIDE + c4 * 4] = v;
        }
        // stage W tile k-major: Ws[kk][n], 32 x 128
#pragma unroll
        for (int it = 0; it < 4; it++) {
            int l = tid + it * 256;
            int kk = l >> 5, nq = l & 31;
            float4 v = *(const float4*)(Wbase + (size_t)(k0 + kk) * ldw + nq * 4);
            *(float4*)&Ws[kk * WS_STRIDE + nq * 4] = v;
        }
        __syncthreads();

#pragma unroll
        for (int kk0 = 0; kk0 < 32; kk0 += 8) {
            uint32_t Ah[2][4], Al[2][4];
#pragma unroll
            for (int mt = 0; mt < 2; mt++) {
                int rb = wm * 32 + mt * 16;
                split_tf32(Xs[(rb + g)     * XS_STRIDE + kk0 + tg],     Ah[mt][0], Al[mt][0]);
                split_tf32(Xs[(rb + g + 8) * XS_STRIDE + kk0 + tg],     Ah[mt][1], Al[mt][1]);
                split_tf32(Xs[(rb + g)     * XS_STRIDE + kk0 + tg + 4], Ah[mt][2], Al[mt][2]);
                split_tf32(Xs[(rb + g + 8) * XS_STRIDE + kk0 + tg + 4], Ah[mt][3], Al[mt][3]);
            }
#pragma unroll
            for (int nt = 0; nt < 8; nt++) {
                int nb = wn * 64 + nt * 8;
                uint32_t b0h, b0l, b1h, b1l;
                split_tf32(Ws[(kk0 + tg)     * WS_STRIDE + nb + g], b0h, b0l);
                split_tf32(Ws[(kk0 + tg + 4) * WS_STRIDE + nb + g], b1h, b1l);
                mma3_tf32(C[0][nt], Ah[0], Al[0], b0h, b1h, b0l, b1l);
                mma3_tf32(C[1][nt], Ah[1], Al[1], b0h, b1h, b0l, b1l);
            }
        }
        __syncthreads();
    }

#pragma unroll
    for (int mt = 0; mt < 2; mt++) {
#pragma unroll
        for (int nt = 0; nt < 8; nt++) {
            int row0 = wm * 32 + mt * 16 + g;
            int col  = wn * 64 + nt * 8 + tg * 2;
            float b0v = HAS_BIAS ? bias[col]     : 0.f;
            float b1v = HAS_BIAS ? bias[col + 1] : 0.f;
            *(float2*)&Obase[(size_t)row0 * ldo + col] =
                make_float2(C[mt][nt][0] + b0v, C[mt][nt][1] + b1v);
            *(float2*)&Obase[(size_t)(row0 + 8) * ldo + col] =
                make_float2(C[mt][nt][2] + b0v, C[mt][nt][3] + b1v);
        }
    }
}

// ---------------------------------------------------------------------------
// QKV projection (3xTF32). grid (T/128, 36), block 256.
// ---------------------------------------------------------------------------
__global__ __launch_bounds__(256, 2) void qkv_proj_tf32_kernel(
    const float* __restrict__ x,
    const float* __restrict__ wq, const float* __restrict__ bq,
    const float* __restrict__ wk, const float* __restrict__ bk,
    const float* __restrict__ wv, const float* __restrict__ bv)
{
    int z = blockIdx.y;
    const float* w; const float* b; float* out;
    if (z < NH)           { w = wq + (size_t)z * DD * HD;        b = bq + z * HD;        out = g_q + (size_t)z * TT * HD; }
    else if (z < NH + KH) { int c = z - NH;      w = wk + (size_t)c * DD * HD; b = bk + c * HD; out = g_k + (size_t)c * TT * HD; }
    else                  { int c = z - NH - KH; w = wv + (size_t)c * DD * HD; b = bv + c * HD; out = g_v + (size_t)c * TT * HD; }

    int t0 = blockIdx.x * 128;
    gemm_core_tf32<true>(x + (size_t)t0 * DD, w, HD, b, out + (size_t)t0 * HD, HD);
}

// ---------------------------------------------------------------------------
// Output projection (3xTF32). grid (T/128, D/128), block 256.
// ---------------------------------------------------------------------------
__global__ __launch_bounds__(256, 2) void out_proj_tf32_kernel(
    const float* __restrict__ wo, float* __restrict__ out)
{
    int t0 = blockIdx.x * 128;
    int n0 = blockIdx.y * 128;
    gemm_core_tf32<false>(g_ctx + (size_t)t0 * DD, wo + n0, DD, nullptr,
                          out + (size_t)t0 * DD + n0, DD);
}

// ---------------------------------------------------------------------------
// RoPE in-place on g_q (with 1/sqrt(H) scale) and g_k. fp64 angle math.
// grid: (T, NH+KH), block 64
// ---------------------------------------------------------------------------
__global__ void rope_kernel(const int* __restrict__ positions)
{
    int t = blockIdx.x;
    int hidx = blockIdx.y;
    int i = threadIdx.x;  // 0..63

    float* base; float scale;
    if (hidx < NH) { base = g_q + ((size_t)hidx * TT + t) * HD; scale = 0.08838834764831845f; }
    else           { base = g_k + ((size_t)(hidx - NH) * TT + t) * HD; scale = 1.0f; }

    int pos = positions[t];
    double inv_freq = pow(1000000.0, -(double)(2 * i) / 128.0);
    double ang = (double)pos * inv_freq;
    double sd, cd;
    sincos(ang, &sd, &cd);
    float c = (float)cd, s = (float)sd;
    float x1 = base[i], x2 = base[i + 64];
    base[i]      = (x1 * c - x2 * s) * scale;
    base[i + 64] = (x2 * c + x1 * s) * scale;
}

// ---------------------------------------------------------------------------
// Flash attention, 3xTF32 tensor cores.
// grid (T/128, NH), block 256 = 8 warps; warp w owns q-rows [16w, 16w+16).
// KV tile = 64. Row softmax stats live in registers (quad-local).
// Shared layouts (floats):
//   Qs[128][132]  (132%32==4 -> A-frag reads conflict-free)
//   Ks[64][132]   (B-frag for S: b=Ks[n][k], bank=(4g+tg) ok)
//   Vs[64][136]   (B-frag for PV: b=Vs[k][n], bank=(8tg+g) ok)
//   Ps[128][68]   (A-frag for PV, warp-local)
// ---------------------------------------------------------------------------
#define FL_QS (128 * 132)
#define FL_KS (64 * 132)
#define FL_VS (64 * 136)
#define FL_PS (128 * 68)
#define FL_SMEM ((FL_QS + FL_KS + FL_VS + FL_PS) * 4)

__global__ __launch_bounds__(256) void flash_tf32_kernel()
{
    extern __shared__ float sm[];
    float* Qs = sm;
    float* Ks = Qs + FL_QS;
    float* Vs = Ks + FL_KS;
    float* Ps = Vs + FL_VS;

    int bq = blockIdx.x;          // q tile of 128 rows
    int n  = blockIdx.y;
    int kvh = n / GQ;
    int tid = threadIdx.x;
    int warp = tid >> 5, lane = tid & 31;
    int g = lane >> 2, tg = lane & 3;

    // stage Q tile (128 x 128)
    const float* qbase = g_q + ((size_t)n * TT + (size_t)bq * 128) * HD;
#pragma unroll
    for (int it = 0; it < 16; it++) {
        int l = tid + it * 256;
        int row = l >> 5, c4 = l & 31;
        *(float4*)&Qs[row * 132 + c4 * 4] = *(const float4*)(qbase + (size_t)row * HD + c4 * 4);
    }

    float O[16][4];
#pragma unroll
    for (int i = 0; i < 16; i++)
#pragma unroll
        for (int r = 0; r < 4; r++) O[i][r] = 0.f;
    float m0 = -1.0e30f, m1 = -1.0e30f, l0 = 0.f, l1 = 0.f;

    int row_loc0 = warp * 16 + g;       // local q row for c[.][0,1]
    int row_loc1 = row_loc0 + 8;        // for c[.][2,3]
    int qrow0 = bq * 128 + row_loc0;
    int qrow1 = qrow0 + 8;

    int jmax = 2 * bq + 1;
    for (int j = 0; j <= jmax; j++) {
        __syncthreads();   // Qs staged (iter 0) / prev-tile Ks,Vs reads done
        const float* kb = g_k + ((size_t)kvh * TT + (size_t)j * 64) * HD;
        const float* vb = g_v + ((size_t)kvh * TT + (size_t)j * 64) * HD;
#pragma unroll
        for (int it = 0; it < 8; it++) {
            int l = tid + it * 256;
            int row = l >> 5, c4 = l & 31;
            *(float4*)&Ks[row * 132 + c4 * 4] = *(const float4*)(kb + (size_t)row * HD + c4 * 4);
            *(float4*)&Vs[row * 136 + c4 * 4] = *(const float4*)(vb + (size_t)row * HD + c4 * 4);
        }
        __syncthreads();

        // ---- S = Q K^T  (16 rows x 64 cols per warp) ----
        float c[8][4];
#pragma unroll
        for (int nt = 0; nt < 8; nt++)
#pragma unroll
            for (int r = 0; r < 4; r++) c[nt][r] = 0.f;

#pragma unroll
        for (int kc = 0; kc < 16; kc++) {
            uint32_t Ah[4], Al[4];
            split_tf32(Qs[row_loc0 * 132 + kc * 8 + tg],     Ah[0], Al[0]);
            split_tf32(Qs[row_loc1 * 132 + kc * 8 + tg],     Ah[1], Al[1]);
            split_tf32(Qs[row_loc0 * 132 + kc * 8 + tg + 4], Ah[2], Al[2]);
            split_tf32(Qs[row_loc1 * 132 + kc * 8 + tg + 4], Ah[3], Al[3]);
#pragma unroll
            for (int nt = 0; nt < 8; nt++) {
                uint32_t b0h, b0l, b1h, b1l;
                split_tf32(Ks[(nt * 8 + g) * 132 + kc * 8 + tg],     b0h, b0l);
                split_tf32(Ks[(nt * 8 + g) * 132 + kc * 8 + tg + 4], b1h, b1l);
                mma3_tf32(c[nt], Ah, Al, b0h, b1h, b0l, b1l);
            }
        }

        // ---- causal mask (only needed near the diagonal) ----
        if (j >= 2 * bq) {
#pragma unroll
            for (int nt = 0; nt < 8; nt++) {
                int col = j * 64 + nt * 8 + tg * 2;
                if (col     > qrow0) c[nt][0] = -1.0e30f;
                if (col + 1 > qrow0) c[nt][1] = -1.0e30f;
                if (col     > qrow1) c[nt][2] = -1.0e30f;
                if (col + 1 > qrow1) c[nt][3] = -1.0e30f;
            }
        }

        // ---- online softmax (quad-local rows) ----
        float mx0 = -1.0e30f, mx1 = -1.0e30f;
#pragma unroll
        for (int nt = 0; nt < 8; nt++) {
            mx0 = fmaxf(mx0, fmaxf(c[nt][0], c[nt][1]));
            mx1 = fmaxf(mx1, fmaxf(c[nt][2], c[nt][3]));
        }
        mx0 = fmaxf(mx0, __shfl_xor_sync(0xFFFFFFFFu, mx0, 1));
        mx0 = fmaxf(mx0, __shfl_xor_sync(0xFFFFFFFFu, mx0, 2));
        mx1 = fmaxf(mx1, __shfl_xor_sync(0xFFFFFFFFu, mx1, 1));
        mx1 = fmaxf(mx1, __shfl_xor_sync(0xFFFFFFFFu, mx1, 2));

        float mn0 = fmaxf(m0, mx0);
        float mn1 = fmaxf(m1, mx1);
        float al0 = __expf(m0 - mn0);
        float al1 = __expf(m1 - mn1);
        float s0 = 0.f, s1 = 0.f;
#pragma unroll
        for (int nt = 0; nt < 8; nt++) {
            c[nt][0] = __expf(c[nt][0] - mn0);
            c[nt][1] = __expf(c[nt][1] - mn0);
            c[nt][2] = __expf(c[nt][2] - mn1);
            c[nt][3] = __expf(c[nt][3] - mn1);
            s0 += c[nt][0] + c[nt][1];
            s1 += c[nt][2] + c[nt][3];
        }
        s0 += __shfl_xor_sync(0xFFFFFFFFu, s0, 1);
        s0 += __shfl_xor_sync(0xFFFFFFFFu, s0, 2);
        s1 += __shfl_xor_sync(0xFFFFFFFFu, s1, 1);
        s1 += __shfl_xor_sync(0xFFFFFFFFu, s1, 2);

        l0 = l0 * al0 + s0;  m0 = mn0;
        l1 = l1 * al1 + s1;  m1 = mn1;

#pragma unroll
        for (int i = 0; i < 16; i++) {
            O[i][0] *= al0; O[i][1] *= al0;
            O[i][2] *= al1; O[i][3] *= al1;
        }

        // ---- write P (warp-local rows) ----
#pragma unroll
        for (int nt = 0; nt < 8; nt++) {
            *(float2*)&Ps[row_loc0 * 68 + nt * 8 + tg * 2] = make_float2(c[nt][0], c[nt][1]);
            *(float2*)&Ps[row_loc1 * 68 + nt * 8 + tg * 2] = make_float2(c[nt][2], c[nt][3]);
        }
        __syncwarp();

        // ---- O += P V  (16 rows x 128 h per warp) ----
#pragma unroll
        for (int kc = 0; kc < 8; kc++) {
            uint32_t Ah[4], Al[4];
            split_tf32(Ps[row_loc0 * 68 + kc * 8 + tg],     Ah[0], Al[0]);
            split_tf32(Ps[row_loc1 * 68 + kc * 8 + tg],     Ah[1], Al[1]);
            split_tf32(Ps[row_loc0 * 68 + kc * 8 + tg + 4], Ah[2], Al[2]);
            split_tf32(Ps[row_loc1 * 68 + kc * 8 + tg + 4], Ah[3], Al[3]);
#pragma unroll
            for (int nt = 0; nt < 16; nt++) {
                uint32_t b0h, b0l, b1h, b1l;
                split_tf32(Vs[(kc * 8 + tg)     * 136 + nt * 8 + g], b0h, b0l);
                split_tf32(Vs[(kc * 8 + tg + 4) * 136 + nt * 8 + g], b1h, b1l);
                mma3_tf32(O[nt], Ah, Al, b0h, b1h, b0l, b1l);
            }
        }
    }

    // ---- epilogue: divide by l, write ctx[t][n*H + h] ----
    float inv0 = 1.f / l0;
    float inv1 = 1.f / l1;
    int t0 = bq * 128 + row_loc0;
    int t1 = t0 + 8;
#pragma unroll
    for (int nt = 0; nt < 16; nt++) {
        int col = n * HD + nt * 8 + tg * 2;
        *(float2*)&g_ctx[(size_t)t0 * DD + col] = make_float2(O[nt][0] * inv0, O[nt][1] * inv0);
        *(float2*)&g_ctx[(size_t)t1 * DD + col] = make_float2(O[nt][2] * inv1, O[nt][3] * inv1);
    }
}

// ---------------------------------------------------------------------------

extern "C" void kernel_launch(void* const* d_in, const int* in_sizes, int n_in,
                              void* d_out, int out_size)
{
    const float* x         = (const float*)d_in[0];
    const int*   positions = (const int*)d_in[1];
    const float* wq        = (const float*)d_in[2];
    const float* bq        = (const float*)d_in[3];
    const float* wk        = (const float*)d_in[4];
    const float* bk        = (const float*)d_in[5];
    const float* wv        = (const float*)d_in[6];
    const float* bv        = (const float*)d_in[7];
    const float* wo        = (const float*)d_in[8];
    float* out = (float*)d_out;

    qkv_proj_tf32_kernel<<<dim3(TT / 128, NH + 2 * KH), 256>>>(x, wq, bq, wk, bk, wv, bv);
    rope_kernel<<<dim3(TT, NH + KH), 64>>>(positions);

    cudaFuncSetAttribute(flash_tf32_kernel, cudaFuncAttributeMaxDynamicSharedMemorySize, FL_SMEM);
    flash_tf32_kernel<<<dim3(TT / 128, NH), 256, FL_SMEM>>>();

    out_proj_tf32_kernel<<<dim3(TT / 128, DD / 128), 256>>>(wo, out);
}